// round 7
// baseline (speedup 1.0000x reference)
#include <cuda_runtime.h>
#include <cstdint>

// 2x nearest-neighbor upsample — phase-coarsened variant.
// in : [16, 64, 256, 256] fp32 = 67108864 floats
// out: [16, 64, 512, 512] fp32
//
// Each thread handles FOUR 32-byte input chunks, spaced by blockDim within
// one block-contiguous region. All 4 loads (ld.nc.v8) are issued up front:
// per warp this forms a 4 KB contiguous read burst followed by a 16 KB
// contiguous write burst, coarsening the read/write phase alternation seen
// by the memory controller without changing traffic.

static constexpr int W8_IN = 32;   // 8-float chunks per input row (256/8)
static constexpr int W_OUT = 512;  // floats per output row
static constexpr int K     = 4;    // chunks per thread

__device__ __forceinline__ void load_v8(const float* p, float* f)
{
    asm volatile(
        "ld.global.nc.v8.f32 {%0,%1,%2,%3,%4,%5,%6,%7}, [%8];"
        : "=f"(f[0]), "=f"(f[1]), "=f"(f[2]), "=f"(f[3]),
          "=f"(f[4]), "=f"(f[5]), "=f"(f[6]), "=f"(f[7])
        : "l"(p));
}

__device__ __forceinline__ void store_patch(float* op, const float* f)
{
    asm volatile(
        "st.global.v8.f32 [%0], {%1,%2,%3,%4,%5,%6,%7,%8};"
        :: "l"(op),
           "f"(f[0]), "f"(f[0]), "f"(f[1]), "f"(f[1]),
           "f"(f[2]), "f"(f[2]), "f"(f[3]), "f"(f[3]) : "memory");
    asm volatile(
        "st.global.v8.f32 [%0], {%1,%2,%3,%4,%5,%6,%7,%8};"
        :: "l"(op + 8),
           "f"(f[4]), "f"(f[4]), "f"(f[5]), "f"(f[5]),
           "f"(f[6]), "f"(f[6]), "f"(f[7]), "f"(f[7]) : "memory");
    asm volatile(
        "st.global.v8.f32 [%0], {%1,%2,%3,%4,%5,%6,%7,%8};"
        :: "l"(op + W_OUT),
           "f"(f[0]), "f"(f[0]), "f"(f[1]), "f"(f[1]),
           "f"(f[2]), "f"(f[2]), "f"(f[3]), "f"(f[3]) : "memory");
    asm volatile(
        "st.global.v8.f32 [%0], {%1,%2,%3,%4,%5,%6,%7,%8};"
        :: "l"(op + W_OUT + 8),
           "f"(f[4]), "f"(f[4]), "f"(f[5]), "f"(f[5]),
           "f"(f[6]), "f"(f[6]), "f"(f[7]), "f"(f[7]) : "memory");
}

__global__ __launch_bounds__(256)
void upsample2x_v8k4_kernel(const float* __restrict__ in,
                            float* __restrict__ out)
{
    // Block covers K * blockDim consecutive chunks; thread t takes
    // chunks base + t + j*blockDim (warp-contiguous within each j).
    int base = blockIdx.x * (blockDim.x * K) + threadIdx.x;

    float f[K][8];
    int   idxs[K];

    #pragma unroll
    for (int j = 0; j < K; j++) {
        idxs[j] = base + j * 256;
        load_v8(in + (size_t)idxs[j] * 8, f[j]);
    }

    #pragma unroll
    for (int j = 0; j < K; j++) {
        int idx  = idxs[j];
        int row  = idx >> 5;          // combined b*c*h row index
        int col8 = idx & (W8_IN - 1);
        float* op = out + (size_t)(row * 2) * W_OUT + (size_t)col8 * 16;
        store_patch(op, f[j]);
    }
}

extern "C" void kernel_launch(void* const* d_in, const int* in_sizes, int n_in,
                              void* d_out, int out_size)
{
    const float* in  = (const float*)d_in[0];
    float*       out = (float*)d_out;

    int n_elems = in_sizes[0];              // 67108864
    int n8      = n_elems / 8;              // 8388608 chunks
    int threads = 256;
    int blocks  = n8 / (threads * K);       // 8192 (divides exactly)

    upsample2x_v8k4_kernel<<<blocks, threads>>>(in, out);
}

// round 8
// speedup vs baseline: 1.0185x; 1.0185x over previous
#include <cuda_runtime.h>
#include <cstdint>

// 2x nearest-neighbor upsample — FINAL (best measured variant, R2 structure).
// in : [16, 64, 256, 256] fp32 = 67108864 floats
// out: [16, 64, 512, 512] fp32
//
// One thread per 32-byte input chunk (8 consecutive input pixels along W):
//   1 x ld.global.v8.f32  +  4 x st.global.v8.f32
// producing a 16-pixel x 2-row output patch. All accesses 256-bit, fully
// coalesced. Kernel is DRAM-bound at ~6.7 TB/s (~84% of 8 TB/s spec), which
// measurement across 6 structural variants shows to be the HBM controller
// ceiling for this 1:4 read:write streaming mix.

static constexpr int W8_IN = 32;   // 8-float chunks per input row (256/8)
static constexpr int W_OUT = 512;  // floats per output row

__global__ __launch_bounds__(256)
void upsample2x_v8_kernel(const float* __restrict__ in,
                          float* __restrict__ out,
                          int n8)
{
    int idx = blockIdx.x * blockDim.x + threadIdx.x;
    if (idx >= n8) return;

    int row  = idx >> 5;          // idx / 32  (combined b*c*h row index)
    int col8 = idx & (W8_IN - 1); // idx % 32

    const float* ip = in + (size_t)idx * 8;

    float f0, f1, f2, f3, f4, f5, f6, f7;
    asm volatile(
        "ld.global.v8.f32 {%0,%1,%2,%3,%4,%5,%6,%7}, [%8];"
        : "=f"(f0), "=f"(f1), "=f"(f2), "=f"(f3),
          "=f"(f4), "=f"(f5), "=f"(f6), "=f"(f7)
        : "l"(ip));

    float* op = out + (size_t)(row * 2) * W_OUT + (size_t)col8 * 16;

    // Row 0: [f0 f0 f1 f1 f2 f2 f3 f3][f4 f4 f5 f5 f6 f6 f7 f7]
    asm volatile(
        "st.global.v8.f32 [%0], {%1,%2,%3,%4,%5,%6,%7,%8};"
        :: "l"(op),
           "f"(f0), "f"(f0), "f"(f1), "f"(f1),
           "f"(f2), "f"(f2), "f"(f3), "f"(f3) : "memory");
    asm volatile(
        "st.global.v8.f32 [%0], {%1,%2,%3,%4,%5,%6,%7,%8};"
        :: "l"(op + 8),
           "f"(f4), "f"(f4), "f"(f5), "f"(f5),
           "f"(f6), "f"(f6), "f"(f7), "f"(f7) : "memory");
    // Row 1 = duplicate of row 0
    asm volatile(
        "st.global.v8.f32 [%0], {%1,%2,%3,%4,%5,%6,%7,%8};"
        :: "l"(op + W_OUT),
           "f"(f0), "f"(f0), "f"(f1), "f"(f1),
           "f"(f2), "f"(f2), "f"(f3), "f"(f3) : "memory");
    asm volatile(
        "st.global.v8.f32 [%0], {%1,%2,%3,%4,%5,%6,%7,%8};"
        :: "l"(op + W_OUT + 8),
           "f"(f4), "f"(f4), "f"(f5), "f"(f5),
           "f"(f6), "f"(f6), "f"(f7), "f"(f7) : "memory");
}

extern "C" void kernel_launch(void* const* d_in, const int* in_sizes, int n_in,
                              void* d_out, int out_size)
{
    const float* in  = (const float*)d_in[0];
    float*       out = (float*)d_out;

    int n_elems = in_sizes[0];          // 67108864
    int n8      = n_elems / 8;          // 8388608 threads

    int threads = 256;
    int blocks  = (n8 + threads - 1) / threads;
    upsample2x_v8_kernel<<<blocks, threads>>>(in, out, n8);
}

// round 9
// speedup vs baseline: 1.0195x; 1.0010x over previous
#include <cuda_runtime.h>
#include <cstdint>

// 2x nearest-neighbor upsample — FINAL.
// in : [16, 64, 256, 256] fp32 = 67108864 floats
// out: [16, 64, 512, 512] fp32
//
// One thread per 32-byte input chunk (8 consecutive input pixels along W):
//   1 x ld.global.v8.f32  +  4 x st.global.v8.f32
// producing a 16-pixel x 2-row output patch. All accesses 256-bit, fully
// coalesced.
//
// Roofline status: DRAM-bound at ~6.65 TB/s (~84% of 8 TB/s spec). Six
// structural variants (vector width, MLP, cache hints, output-centric,
// phase-coarsening, block size) all plateau at 6.55-6.68 TB/s with SM pipes
// <10% busy — this is the HBM controller ceiling for a 1:4 R:W streaming
// mix, and the 1.34 GB of traffic is mandatory. Kernel is at roofline.

static constexpr int W8_IN = 32;   // 8-float chunks per input row (256/8)
static constexpr int W_OUT = 512;  // floats per output row

__global__ __launch_bounds__(256)
void upsample2x_v8_kernel(const float* __restrict__ in,
                          float* __restrict__ out,
                          int n8)
{
    int idx = blockIdx.x * blockDim.x + threadIdx.x;
    if (idx >= n8) return;

    int row  = idx >> 5;          // idx / 32  (combined b*c*h row index)
    int col8 = idx & (W8_IN - 1); // idx % 32

    const float* ip = in + (size_t)idx * 8;

    float f0, f1, f2, f3, f4, f5, f6, f7;
    asm volatile(
        "ld.global.v8.f32 {%0,%1,%2,%3,%4,%5,%6,%7}, [%8];"
        : "=f"(f0), "=f"(f1), "=f"(f2), "=f"(f3),
          "=f"(f4), "=f"(f5), "=f"(f6), "=f"(f7)
        : "l"(ip));

    float* op = out + (size_t)(row * 2) * W_OUT + (size_t)col8 * 16;

    // Row 0: [f0 f0 f1 f1 f2 f2 f3 f3][f4 f4 f5 f5 f6 f6 f7 f7]
    asm volatile(
        "st.global.v8.f32 [%0], {%1,%2,%3,%4,%5,%6,%7,%8};"
        :: "l"(op),
           "f"(f0), "f"(f0), "f"(f1), "f"(f1),
           "f"(f2), "f"(f2), "f"(f3), "f"(f3) : "memory");
    asm volatile(
        "st.global.v8.f32 [%0], {%1,%2,%3,%4,%5,%6,%7,%8};"
        :: "l"(op + 8),
           "f"(f4), "f"(f4), "f"(f5), "f"(f5),
           "f"(f6), "f"(f6), "f"(f7), "f"(f7) : "memory");
    // Row 1 = duplicate of row 0
    asm volatile(
        "st.global.v8.f32 [%0], {%1,%2,%3,%4,%5,%6,%7,%8};"
        :: "l"(op + W_OUT),
           "f"(f0), "f"(f0), "f"(f1), "f"(f1),
           "f"(f2), "f"(f2), "f"(f3), "f"(f3) : "memory");
    asm volatile(
        "st.global.v8.f32 [%0], {%1,%2,%3,%4,%5,%6,%7,%8};"
        :: "l"(op + W_OUT + 8),
           "f"(f4), "f"(f4), "f"(f5), "f"(f5),
           "f"(f6), "f"(f6), "f"(f7), "f"(f7) : "memory");
}

extern "C" void kernel_launch(void* const* d_in, const int* in_sizes, int n_in,
                              void* d_out, int out_size)
{
    const float* in  = (const float*)d_in[0];
    float*       out = (float*)d_out;

    int n_elems = in_sizes[0];          // 67108864
    int n8      = n_elems / 8;          // 8388608 threads

    int threads = 256;
    int blocks  = (n8 + threads - 1) / threads;
    upsample2x_v8_kernel<<<blocks, threads>>>(in, out, n8);
}